// round 15
// baseline (speedup 1.0000x reference)
#include <cuda_runtime.h>
#include <cuda_fp16.h>
#include <math_constants.h>
#include <cstdint>

#define BB 2
#define C 256
#define CI 128
#define NN 6400
#define NH (NN / 2)
#define SPLITK 8
#define NBLK (NN / 128)     // 50

typedef unsigned u32;

// ---------------- scratch (all fp16 arrays are plain-half, col-contiguous) --
__device__ __half d_Xh[BB * C * NN];                   // x [c][n]
__device__ __half d_Wh[C * 384];                       // proj weights [c][which*128+o]
__device__ __half d_Th[BB * CI * NN];                  // theta [c][n]
__device__ __half d_Ph[BB * CI * NN];                  // phi   [c][n]
__device__ __half d_Gh[BB * CI * NN];                  // g proj half [c][m]
__device__ u32    d_Sh[(size_t)BB * NN * NH];          // S = exp(f-tileMax): half [n][m]
__device__ float  d_pM[BB * NBLK * NN];
__device__ float  d_pS[BB * NBLK * NN];
__device__ __half d_corr[BB * NBLK * NN];              // corr [nblk][m]
__device__ __half d_GSh[BB * NN * CI];                 // g [m][c]
__device__ u32    d_YPh[(size_t)SPLITK * BB * NN * (CI / 2)]; // fp16 split-K partials [n][c2]
__device__ __half d_Yh[BB * CI * NN];                  // y [c][n]
__device__ __half d_Wt[CI * C];                        // Ww^T [ci][m]

// ============================================================================
//                    fp16 mma + ldmatrix machinery
// ============================================================================
__device__ __forceinline__ u32 packh2(float a, float b) {
    __half2 h = __halves2half2(__float2half_rn(a), __float2half_rn(b));
    return reinterpret_cast<u32&>(h);
}
__device__ __forceinline__ u32 pack2h(__half a, __half b) {
    __half2 h = __halves2half2(a, b);
    return reinterpret_cast<u32&>(h);
}
__device__ __forceinline__ u32 hmul_u32(u32 a, u32 b) {
    __half2 r = __hmul2(reinterpret_cast<__half2&>(a), reinterpret_cast<__half2&>(b));
    return reinterpret_cast<u32&>(r);
}
__device__ __forceinline__ void mma_f16(float c[4], const u32 a[4], const u32 b[2]) {
    asm volatile(
        "mma.sync.aligned.m16n8k16.row.col.f32.f16.f16.f32 "
        "{%0,%1,%2,%3}, {%4,%5,%6,%7}, {%8,%9}, {%0,%1,%2,%3};"
        : "+f"(c[0]), "+f"(c[1]), "+f"(c[2]), "+f"(c[3])
        : "r"(a[0]), "r"(a[1]), "r"(a[2]), "r"(a[3]), "r"(b[0]), "r"(b[1]));
}
#define LDSM4(d, a) \
    asm volatile("ldmatrix.sync.aligned.m8n8.x4.shared.b16 {%0,%1,%2,%3}, [%4];" \
        : "=r"((d)[0]), "=r"((d)[1]), "=r"((d)[2]), "=r"((d)[3]) : "r"(a))
#define LDSM4T(d, a) \
    asm volatile("ldmatrix.sync.aligned.m8n8.x4.trans.shared.b16 {%0,%1,%2,%3}, [%4];" \
        : "=r"((d)[0]), "=r"((d)[1]), "=r"((d)[2]), "=r"((d)[3]) : "r"(a))

__device__ __forceinline__ u32 smem_u32p(const void* p) {
    return (u32)__cvta_generic_to_shared(p);
}
#define CP16(dst, src) asm volatile("cp.async.cg.shared.global [%0], [%1], 16;" :: "r"(dst), "l"(src))
#define CPC()          asm volatile("cp.async.commit_group;")
#define CPW(n)         asm volatile("cp.async.wait_group %0;" :: "n"(n))
#define STS128A(addr, a, b, c, d) \
    asm volatile("st.shared.v4.b32 [%0], {%1,%2,%3,%4};" :: "r"(addr), "r"(a), "r"(b), "r"(c), "r"(d) : "memory")

#define ACC_INIT()                                      \
    float acc[2][8][4];                                 \
    _Pragma("unroll") for (int i = 0; i < 2; i++)       \
    _Pragma("unroll") for (int j = 0; j < 8; j++)       \
    _Pragma("unroll") for (int r = 0; r < 4; r++) acc[i][j][r] = 0.f;

// ldmatrix addr precompute (KTILE = [32 k rows][128 cols] half, 256B rows,
// chunk swizzle c' = c ^ (k&7))
#define KT_ADDRS(adA, adB, base_a, base_b)                               \
    u32 adA[2], adB[4];                                                  \
    {                                                                    \
        const int kA = (lane & 7) + ((lane >> 4) & 1) * 8;               \
        const int oA = (lane >> 3) & 1;                                  \
        _Pragma("unroll")                                                \
        for (int mt = 0; mt < 2; mt++) {                                 \
            const int chk = wm * 4 + mt * 2 + oA;                        \
            adA[mt] = (base_a) + kA * 256 + ((chk ^ (lane & 7)) << 4);   \
        }                                                                \
        const int kB = (lane & 7) + ((lane >> 3) & 1) * 8;               \
        const int oB = (lane >> 4) & 1;                                  \
        _Pragma("unroll")                                                \
        for (int p = 0; p < 4; p++) {                                    \
            const int chk = wn * 8 + p * 2 + oB;                         \
            adB[p] = (base_b) + kB * 256 + ((chk ^ (lane & 7)) << 4);    \
        }                                                                \
    }

#define FCOMP_TT(so)                                                     \
    _Pragma("unroll")                                                    \
    for (int s16 = 0; s16 < 2; ++s16) {                                  \
        const u32 o16 = (so) + s16 * 4096;                               \
        u32 af[2][4], bq[4][4];                                          \
        LDSM4T(af[0], adA[0] + o16);                                     \
        LDSM4T(af[1], adA[1] + o16);                                     \
        _Pragma("unroll")                                                \
        for (int p = 0; p < 4; p++) LDSM4T(bq[p], adB[p] + o16);         \
        _Pragma("unroll")                                                \
        for (int mt = 0; mt < 2; mt++)                                   \
            _Pragma("unroll")                                            \
            for (int p = 0; p < 4; p++) {                                \
                u32 b0[2] = {bq[p][0], bq[p][1]};                        \
                u32 b1[2] = {bq[p][2], bq[p][3]};                        \
                mma_f16(acc[mt][2 * p],     af[mt], b0);                 \
                mma_f16(acc[mt][2 * p + 1], af[mt], b1);                 \
            }                                                            \
    }

#define KT_CP(dstBase, srcPtr, pitch)                                            \
    {                                                                            \
        const int kr = t >> 3, c0k = t & 7;                                      \
        const __half* sp_ = (srcPtr) + (size_t)kr * (pitch);                     \
        CP16((dstBase) + kr * 256 + (((c0k)     ^ (kr & 7)) << 4), sp_ + c0k * 8);       \
        CP16((dstBase) + kr * 256 + (((c0k + 8) ^ (kr & 7)) << 4), sp_ + (c0k + 8) * 8); \
    }

// ---------------- 0: fused packing (x, proj weights, Ww^T) -----------------
#define PX_N (BB * C * NH)          // 1,638,400 u32 stores
#define PW_N (C * 384)              // 98,304 half stores
#define WT_N (CI * C / 2)           // 16,384 u32 stores
__global__ void pack_all_kernel(const float* __restrict__ x,
                                const float* __restrict__ tw,
                                const float* __restrict__ pw,
                                const float* __restrict__ gw,
                                const float* __restrict__ Ww) {
    const int id = blockIdx.x * 256 + threadIdx.x;
    if (id < PX_N) {
        const int n2 = id % NH;
        const int c  = (id / NH) % C;
        const int b  = id / (NH * C);
        const float2 v = *(const float2*)(x + ((size_t)b * C + c) * NN + 2 * n2);
        *(u32*)(d_Xh + ((size_t)b * C + c) * NN + 2 * n2) = packh2(v.x, v.y);
    } else if (id < PX_N + PW_N) {
        const int i = id - PX_N;
        const int c = i / 384, col = i % 384;
        const int which = col >> 7, o = col & 127;
        const float* W = (which == 0) ? tw : (which == 1) ? pw : gw;
        d_Wh[i] = __float2half_rn(W[o * C + c]);
    } else if (id < PX_N + PW_N + WT_N) {
        const int i = id - PX_N - PW_N;
        const int ci = i >> 7, m2 = i & 127;
        *(u32*)(d_Wt + ci * C + 2 * m2) =
            packh2(Ww[(2 * m2) * CI + ci], Ww[(2 * m2 + 1) * CI + ci]);
    }
}

// ---------------- 1: projections (fp16 mma + ldmatrix) ---------------------
__global__ void __launch_bounds__(256, 2) proj_kernel(const float* __restrict__ tb,
                                                      const float* __restrict__ pb,
                                                      const float* __restrict__ gb) {
    __shared__ u32 As[3][2048];
    __shared__ u32 Bs[3][2048];
    const int t = threadIdx.x, lane = t & 31, warp = t >> 5;
    const int wm = warp & 3, wn = warp >> 2;
    const int g = lane >> 2, tig = lane & 3;
    const u32 aB = smem_u32p(As), bB = smem_u32p(Bs);
    KT_ADDRS(adA, adB, aB, bB);

    const int tile = blockIdx.x;                         // 0..299
    const int b = tile / 150;
    const int rem = tile % 150;
    const int which = rem / 50;
    const int n0 = (rem % 50) * 128;
    const __half* Xh = d_Xh + (size_t)b * C * NN;
    const float* bias = (which == 0) ? tb : (which == 1) ? pb : gb;
    ACC_INIT();

    auto issue = [&](int ch, int s) {
        KT_CP(aB + s * 8192, d_Wh + (size_t)(ch * 32) * 384 + which * 128, 384);
        KT_CP(bB + s * 8192, Xh + (size_t)(ch * 32) * NN + n0, NN);
        CPC();
    };
    issue(0, 0); issue(1, 1);
    #pragma unroll
    for (int ch = 0; ch < 8; ++ch) {
        if (ch + 1 < 8) { CPW(1); } else { CPW(0); }
        __syncthreads();
        if (ch + 2 < 8) issue(ch + 2, (ch + 2) % 3);
        FCOMP_TT((ch % 3) * 8192);
    }

    __half* dst = ((which == 0) ? d_Th : (which == 1) ? d_Ph : d_Gh) + (size_t)b * CI * NN;
    #pragma unroll
    for (int mt = 0; mt < 2; mt++) {
        const int r = wm * 32 + mt * 16 + g;
        const float bv0 = bias[r], bv8 = bias[r + 8];
        #pragma unroll
        for (int nt = 0; nt < 8; nt++) {
            const int n = n0 + wn * 64 + nt * 8 + tig * 2;
            *(u32*)(dst + (size_t)r * NN + n) =
                packh2(acc[mt][nt][0] + bv0, acc[mt][nt][1] + bv0);
            *(u32*)(dst + (size_t)(r + 8) * NN + n) =
                packh2(acc[mt][nt][2] + bv8, acc[mt][nt][3] + bv8);
        }
    }
}

// ---------------- 2: f = theta^T phi ; store S fp16 + stats ----------------
__global__ void __launch_bounds__(256, 2) fgemm_kernel() {
    __shared__ u32 As[3][2048];
    __shared__ u32 Bs[3][2048];
    const int b  = blockIdx.z;
    const int n0 = blockIdx.y * 128;
    const int m0 = blockIdx.x * 128;
    const __half* Th = d_Th + (size_t)b * CI * NN;
    const __half* Ph = d_Ph + (size_t)b * CI * NN;
    u32* S = d_Sh + (size_t)b * NN * NH;

    const int t = threadIdx.x, lane = t & 31, warp = t >> 5;
    const int wm = warp & 3, wn = warp >> 2;
    const int g = lane >> 2, tig = lane & 3;
    const u32 aB = smem_u32p(As), bB = smem_u32p(Bs);
    KT_ADDRS(adA, adB, aB, bB);
    ACC_INIT();

    auto issue = [&](int ch, int s) {
        KT_CP(aB + s * 8192, Th + (size_t)(ch * 32) * NN + n0, NN);
        KT_CP(bB + s * 8192, Ph + (size_t)(ch * 32) * NN + m0, NN);
        CPC();
    };
    issue(0, 0); issue(1, 1);
    #pragma unroll
    for (int ch = 0; ch < 4; ++ch) {
        if (ch + 1 < 4) { CPW(1); } else { CPW(0); }
        __syncthreads();
        if (ch + 2 < 4) issue(ch + 2, (ch + 2) % 3);
        FCOMP_TT((ch % 3) * 8192);
    }

    // ---- column-softmax, slim epilogue: 3 syncs, disjoint max/sum regions -
    __syncthreads();                                     // FCOMP reads of As done
    float* red = (float*)As;                             // max: [0..512), sums: [640..1152)
    float lv[8][2];
    #pragma unroll
    for (int nt = 0; nt < 8; nt++) {
        lv[nt][0] = fmaxf(fmaxf(acc[0][nt][0], acc[0][nt][2]), fmaxf(acc[1][nt][0], acc[1][nt][2]));
        lv[nt][1] = fmaxf(fmaxf(acc[0][nt][1], acc[0][nt][3]), fmaxf(acc[1][nt][1], acc[1][nt][3]));
        #pragma unroll
        for (int d = 4; d <= 16; d <<= 1) {
            lv[nt][0] = fmaxf(lv[nt][0], __shfl_xor_sync(0xffffffff, lv[nt][0], d));
            lv[nt][1] = fmaxf(lv[nt][1], __shfl_xor_sync(0xffffffff, lv[nt][1], d));
        }
    }
    if (g == 0) {
        #pragma unroll
        for (int nt = 0; nt < 8; nt++) {
            const int col = wn * 64 + nt * 8 + tig * 2;
            red[wm * 128 + col]     = lv[nt][0];
            red[wm * 128 + col + 1] = lv[nt][1];
        }
    }
    __syncthreads();
    #pragma unroll
    for (int nt = 0; nt < 8; nt++) {
        const int col = wn * 64 + nt * 8 + tig * 2;
        const float tm0 = fmaxf(fmaxf(red[col],     red[128 + col]),
                                fmaxf(red[256 + col], red[384 + col]));
        const float tm1 = fmaxf(fmaxf(red[col + 1], red[129 + col]),
                                fmaxf(red[257 + col], red[385 + col]));
        float s0 = 0.f, s1 = 0.f;
        #pragma unroll
        for (int mt = 0; mt < 2; mt++) {
            const int n = n0 + wm * 32 + mt * 16 + g;
            const float e0 = __expf(acc[mt][nt][0] - tm0);
            const float e1 = __expf(acc[mt][nt][1] - tm1);
            const float e2 = __expf(acc[mt][nt][2] - tm0);
            const float e3 = __expf(acc[mt][nt][3] - tm1);
            const size_t m2 = (size_t)((m0 + col) >> 1);
            S[(size_t)n * NH + m2]       = packh2(e0, e1);
            S[(size_t)(n + 8) * NH + m2] = packh2(e2, e3);
            s0 += e0 + e2; s1 += e1 + e3;
        }
        #pragma unroll
        for (int d = 4; d <= 16; d <<= 1) {
            s0 += __shfl_xor_sync(0xffffffff, s0, d);
            s1 += __shfl_xor_sync(0xffffffff, s1, d);
        }
        lv[nt][0] = s0; lv[nt][1] = s1;
    }
    if (g == 0) {                                        // disjoint region: no sync needed first
        #pragma unroll
        for (int nt = 0; nt < 8; nt++) {
            const int col = wn * 64 + nt * 8 + tig * 2;
            red[640 + wm * 128 + col]     = lv[nt][0];
            red[640 + wm * 128 + col + 1] = lv[nt][1];
        }
    }
    __syncthreads();
    if (t < 128) {
        const float tm = fmaxf(fmaxf(red[t], red[128 + t]), fmaxf(red[256 + t], red[384 + t]));
        const float s  = red[640 + t] + red[768 + t] + red[896 + t] + red[1024 + t];
        const size_t idx = ((size_t)b * NBLK + blockIdx.y) * NN + m0 + t;
        d_pM[idx] = tm;
        d_pS[idx] = s;
    }
}

// ---------------- 3+4 fused: g transpose AND softmax-stat merge ------------
#define GS_BLOCKS 800
__global__ void __launch_bounds__(512) small_fused_kernel() {
    __shared__ __half sg[32][68];
    __shared__ float2 red[16][32];
    __shared__ float2 resM[32], resR[32];
    const int t = threadIdx.x;
    const int id = blockIdx.x;

    if (id < GS_BLOCKS) {
        const int m0 = (id % 100) * 64;
        const int c0 = ((id / 100) % 4) * 32;
        const int b  = id / 400;
        #pragma unroll
        for (int r = 0; r < 2; r++) {
            const int idx = t + 512 * r;
            const int row = idx >> 5;
            const int cp  = idx & 31;
            *(u32*)&sg[row][cp * 2] =
                *(const u32*)(d_Gh + ((size_t)b * CI + c0 + row) * NN + m0 + cp * 2);
        }
        __syncthreads();
        #pragma unroll
        for (int r = 0; r < 2; r++) {
            const int idx = t + 512 * r;
            const int mm = idx >> 4;
            const int cp = idx & 15;
            *(u32*)(d_GSh + ((size_t)b * NN + m0 + mm) * CI + c0 + 2 * cp) =
                pack2h(sg[2 * cp][mm], sg[2 * cp + 1][mm]);
        }
    } else {
        const int id2 = id - GS_BLOCKS;
        const int b = id2 / 100;
        const int lane = t & 31, seg = t >> 5;
        const int m2 = (id2 % 100) * 32 + lane;
        const float* pM = d_pM + (size_t)b * NBLK * NN + 2 * m2;
        const float* pS = d_pS + (size_t)b * NBLK * NN + 2 * m2;

        float2 vm[4];
        int cnt = 0;
        float M0 = -CUDART_INF_F, M1 = -CUDART_INF_F;
        for (int i = seg; i < NBLK; i += 16) {
            vm[cnt] = *(const float2*)(pM + (size_t)i * NN);
            M0 = fmaxf(M0, vm[cnt].x); M1 = fmaxf(M1, vm[cnt].y);
            cnt++;
        }
        red[seg][lane] = make_float2(M0, M1);
        __syncthreads();
        if (seg == 0) {
            #pragma unroll
            for (int j = 1; j < 16; j++) {
                M0 = fmaxf(M0, red[j][lane].x);
                M1 = fmaxf(M1, red[j][lane].y);
            }
            resM[lane] = make_float2(M0, M1);
        }
        __syncthreads();
        M0 = resM[lane].x; M1 = resM[lane].y;

        float s0 = 0.f, s1 = 0.f;
        {
            int k = 0;
            for (int i = seg; i < NBLK; i += 16, k++) {
                const float2 vs = *(const float2*)(pS + (size_t)i * NN);
                s0 += vs.x * __expf(vm[k].x - M0);
                s1 += vs.y * __expf(vm[k].y - M1);
            }
        }
        red[seg][lane] = make_float2(s0, s1);
        __syncthreads();
        if (seg == 0) {
            #pragma unroll
            for (int j = 1; j < 16; j++) {
                s0 += red[j][lane].x;
                s1 += red[j][lane].y;
            }
            resR[lane] = make_float2(1.f / s0, 1.f / s1);
        }
        __syncthreads();
        const float R0 = resR[lane].x, R1 = resR[lane].y;
        {
            __half* cw = d_corr + (size_t)b * NBLK * NN + 2 * m2;
            int k = 0;
            for (int i = seg; i < NBLK; i += 16, k++)
                *(u32*)(cw + (size_t)i * NN) =
                    packh2(__expf(vm[k].x - M0) * R0, __expf(vm[k].y - M1) * R1);
        }
    }
}

// ---------------- 5: y = (S*corr) g  (ldmatrix fp16 mma, split-K) ----------
__global__ void __launch_bounds__(256, 2) ygemm_kernel() {
    __shared__ u32 As[3][2048];                          // S tile [128 n][32 k] half
    __shared__ u32 Bs[3][2048];                          // B' tile [32 k][128 c] half
    const int b     = blockIdx.z;
    const int split = blockIdx.y;
    const int n0    = blockIdx.x * 128;
    const __half* S   = (const __half*)(const void*)(d_Sh + (size_t)b * NN * NH);
    const __half* GSh = d_GSh + (size_t)b * NN * CI;
    const __half* corrh = d_corr + ((size_t)b * NBLK + blockIdx.x) * NN;
    u32* YP = d_YPh + ((size_t)split * BB + b) * NN * (CI / 2);
    const int kbase = split * (NN / SPLITK);             // 800 per split
    const int NCH   = (NN / SPLITK) / 32;                // 25

    const int t = threadIdx.x, lane = t & 31, warp = t >> 5;
    const int wm = warp & 3, wn = warp >> 2;
    const int g = lane >> 2, tig = lane & 3;
    const u32 aB = smem_u32p(As), bB = smem_u32p(Bs);
    ACC_INIT();

    u32 adAy[2][2];
    {
        const int nl = lane & 15, kh = (lane >> 4) & 1;
        #pragma unroll
        for (int mt = 0; mt < 2; mt++) {
            const int n = wm * 32 + mt * 16 + nl;
            #pragma unroll
            for (int s16 = 0; s16 < 2; s16++) {
                const int chk = s16 * 2 + kh;
                adAy[mt][s16] = aB + n * 64 + ((chk ^ ((n >> 1) & 3)) << 4);
            }
        }
    }
    u32 adB[4];
    {
        const int kB = (lane & 7) + ((lane >> 3) & 1) * 8;
        const int oB = (lane >> 4) & 1;
        #pragma unroll
        for (int p = 0; p < 4; p++) {
            const int chk = wn * 8 + p * 2 + oB;
            adB[p] = bB + kB * 256 + ((chk ^ (lane & 7)) << 4);
        }
    }

    auto issueA = [&](int ch, int s) {
        const int nr = t >> 1, cc = (t & 1) * 2;
        const __half* sp = S + (size_t)(n0 + nr) * NN + kbase + ch * 32;
        const u32 dst = aB + s * 8192 + nr * 64;
        CP16(dst + (((cc)     ^ ((nr >> 1) & 3)) << 4), sp + cc * 8);
        CP16(dst + (((cc + 1) ^ ((nr >> 1) & 3)) << 4), sp + (cc + 1) * 8);
        CPC();
    };
    const int rowB = t >> 3, cB = t & 7;
    uint4 gv[2]; __half crh;
    auto ldB = [&](int ch) {
        const int m = kbase + ch * 32 + rowB;
        const __half* gp = GSh + (size_t)m * CI;
        gv[0] = *(const uint4*)(gp + cB * 8);
        gv[1] = *(const uint4*)(gp + (cB + 8) * 8);
        crh = corrh[m];
    };
    auto stsB = [&](int s) {
        const __half2 crs2 = __half2half2(crh);
        const u32 crs = reinterpret_cast<const u32&>(crs2);
        const u32 dst = bB + s * 8192 + rowB * 256;
        #pragma unroll
        for (int i = 0; i < 2; i++) {
            uint4 w = gv[i];
            STS128A(dst + (((cB + 8 * i) ^ (rowB & 7)) << 4),
                    hmul_u32(w.x, crs), hmul_u32(w.y, crs),
                    hmul_u32(w.z, crs), hmul_u32(w.w, crs));
        }
    };

    ldB(0); issueA(0, 0); issueA(1, 1);
    for (int ch = 0; ch < NCH; ++ch) {
        if (ch + 1 < NCH) { CPW(1); } else { CPW(0); }
        stsB(ch % 3);
        __syncthreads();
        if (ch + 1 < NCH) ldB(ch + 1);
        if (ch + 2 < NCH) issueA(ch + 2, (ch + 2) % 3);
        const u32 so = (ch % 3) * 8192;
        #pragma unroll
        for (int s16 = 0; s16 < 2; ++s16) {
            u32 af[2][4], bq[4][4];
            LDSM4(af[0], adAy[0][s16] + so);
            LDSM4(af[1], adAy[1][s16] + so);
            #pragma unroll
            for (int p = 0; p < 4; p++) LDSM4T(bq[p], adB[p] + so + s16 * 4096);
            #pragma unroll
            for (int mt = 0; mt < 2; mt++)
                #pragma unroll
                for (int p = 0; p < 4; p++) {
                    u32 b0[2] = {bq[p][0], bq[p][1]};
                    u32 b1[2] = {bq[p][2], bq[p][3]};
                    mma_f16(acc[mt][2 * p],     af[mt], b0);
                    mma_f16(acc[mt][2 * p + 1], af[mt], b1);
                }
        }
    }

    // packed fp16 partial store: u32 per (n, c-pair)
    #pragma unroll
    for (int mt = 0; mt < 2; mt++) {
        #pragma unroll
        for (int nt = 0; nt < 8; nt++) {
            const int n  = n0 + wm * 32 + mt * 16 + g;
            const int c2 = wn * 32 + nt * 4 + tig;
            YP[(size_t)n * (CI / 2) + c2]       = packh2(acc[mt][nt][0], acc[mt][nt][1]);
            YP[(size_t)(n + 8) * (CI / 2) + c2] = packh2(acc[mt][nt][2], acc[mt][nt][3]);
        }
    }
}

// ---------------- 6: merge fp16 split-K + transpose -> half [c][n] ---------
__global__ void __launch_bounds__(256) reduceY_kernel() {
    __shared__ float tsm[64][33];                        // [c-local][n-local]
    const int b  = blockIdx.z;
    const int n0 = blockIdx.x * 32;
    const int c0 = blockIdx.y * 64;
    const int t  = threadIdx.x;
    const size_t SS = (size_t)BB * NN * (CI / 2);
    const size_t base = (size_t)b * NN * (CI / 2);
    #pragma unroll
    for (int r = 0; r < 4; r++) {
        const int idx = t + 256 * r;                     // 0..1023
        const int nl = idx >> 5;                         // 0..31
        const int cp = idx & 31;                         // c2-local 0..31
        const size_t off = base + (size_t)(n0 + nl) * (CI / 2) + (c0 >> 1) + cp;
        float s0 = 0.f, s1 = 0.f;
        #pragma unroll
        for (int sp = 0; sp < SPLITK; sp++) {
            const u32 w = d_YPh[sp * SS + off];
            const __half2 h = reinterpret_cast<const __half2&>(w);
            s0 += __low2float(h); s1 += __high2float(h);
        }
        tsm[2 * cp][nl] = s0; tsm[2 * cp + 1][nl] = s1;
    }
    __syncthreads();
    #pragma unroll
    for (int r = 0; r < 4; r++) {
        const int idx = t + 256 * r;
        const int cl = idx >> 4;                         // 0..63
        const int np = idx & 15;                         // 0..15
        *(u32*)(d_Yh + ((size_t)b * CI + c0 + cl) * NN + n0 + 2 * np) =
            packh2(tsm[cl][2 * np], tsm[cl][2 * np + 1]);
    }
}

// ---------------- 9: out = Ww·y + Wb + x  (ldmatrix fp16 mma) --------------
__global__ void __launch_bounds__(256, 2) out_kernel(const float* __restrict__ x,
                                                     const float* __restrict__ Wb,
                                                     float* __restrict__ out) {
    __shared__ u32 As[3][2048];
    __shared__ u32 Bs[3][2048];
    const int b  = blockIdx.z;
    const int m0 = blockIdx.y * 128;
    const int n0 = blockIdx.x * 128;
    const __half* Yh = d_Yh + (size_t)b * CI * NN;

    const int t = threadIdx.x, lane = t & 31, warp = t >> 5;
    const int wm = warp & 3, wn = warp >> 2;
    const int g = lane >> 2, tig = lane & 3;
    const u32 aB = smem_u32p(As), bB = smem_u32p(Bs);
    KT_ADDRS(adA, adB, aB, bB);
    ACC_INIT();

    auto issue = [&](int ch, int s) {
        KT_CP(aB + s * 8192, d_Wt + (size_t)(ch * 32) * C + m0, C);
        KT_CP(bB + s * 8192, Yh + (size_t)(ch * 32) * NN + n0, NN);
        CPC();
    };
    issue(0, 0); issue(1, 1);
    #pragma unroll
    for (int ch = 0; ch < 4; ++ch) {
        if (ch + 1 < 4) { CPW(1); } else { CPW(0); }
        __syncthreads();
        if (ch + 2 < 4) issue(ch + 2, (ch + 2) % 3);
        FCOMP_TT((ch % 3) * 8192);
    }

    #pragma unroll
    for (int mt = 0; mt < 2; mt++) {
        #pragma unroll
        for (int nt = 0; nt < 8; nt++) {
            const int m = m0 + wm * 32 + mt * 16 + g;
            const int n = n0 + wn * 64 + nt * 8 + tig * 2;
            {
                const float bv = Wb[m];
                const float2 xv = *(const float2*)(x + ((size_t)b * C + m) * NN + n);
                *(float2*)(out + ((size_t)b * C + m) * NN + n) =
                    make_float2(acc[mt][nt][0] + bv + xv.x, acc[mt][nt][1] + bv + xv.y);
            }
            {
                const float bv = Wb[m + 8];
                const float2 xv = *(const float2*)(x + ((size_t)b * C + m + 8) * NN + n);
                *(float2*)(out + ((size_t)b * C + m + 8) * NN + n) =
                    make_float2(acc[mt][nt][2] + bv + xv.x, acc[mt][nt][3] + bv + xv.y);
            }
        }
    }
}

// ---------------------------------------------------------------------------
extern "C" void kernel_launch(void* const* d_in, const int* in_sizes, int n_in,
                              void* d_out, int out_size) {
    const float* x  = (const float*)d_in[0];
    const float* gw = (const float*)d_in[1];
    const float* gb = (const float*)d_in[2];
    const float* tw = (const float*)d_in[3];
    const float* tb = (const float*)d_in[4];
    const float* pw = (const float*)d_in[5];
    const float* pb = (const float*)d_in[6];
    const float* Ww = (const float*)d_in[7];
    const float* Wb = (const float*)d_in[8];
    float* out = (float*)d_out;

    pack_all_kernel<<<(PX_N + PW_N + WT_N + 255) / 256, 256>>>(x, tw, pw, gw, Ww);
    proj_kernel<<<300, 256>>>(tb, pb, gb);
    fgemm_kernel<<<dim3(NN / 128, NN / 128, BB), 256>>>();
    small_fused_kernel<<<GS_BLOCKS + (NH / 32) * BB, 512>>>();
    ygemm_kernel<<<dim3(NN / 128, SPLITK, BB), 256>>>();
    reduceY_kernel<<<dim3(NN / 32, CI / 64, BB), 256>>>();
    out_kernel<<<dim3(NN / 128, C / 128, BB), 256>>>(x, Wb, out);
}

// round 16
// speedup vs baseline: 1.0167x; 1.0167x over previous
#include <cuda_runtime.h>
#include <cuda_fp16.h>
#include <math_constants.h>
#include <cstdint>

#define BB 2
#define C 256
#define CI 128
#define NN 6400
#define NH (NN / 2)
#define SPLITK 8
#define NBLK (NN / 128)     // 50

typedef unsigned u32;

// ---------------- scratch (all fp16 arrays are plain-half, col-contiguous) --
__device__ __half d_Xh[BB * C * NN];                   // x [c][n]
__device__ __half d_Wh[C * 384];                       // proj weights [c][which*128+o]
__device__ __half d_Th[BB * CI * NN];                  // theta [c][n]
__device__ __half d_Ph[BB * CI * NN];                  // phi   [c][n]
__device__ u32    d_Sh[(size_t)BB * NN * NH];          // S = exp(f-tileMax): half [n][m]
__device__ float  d_pM[BB * NBLK * NN];
__device__ float  d_pS[BB * NBLK * NN];
__device__ __half d_corr[BB * NBLK * NN];              // corr [nblk][m]
__device__ __half d_GSh[BB * NN * CI];                 // g [m][c]
__device__ u32    d_YPh[(size_t)SPLITK * BB * NN * (CI / 2)]; // fp16 split-K partials [n][c2]
__device__ __half d_Yh[BB * CI * NN];                  // y [c][n]
__device__ __half d_Wt[CI * C];                        // Ww^T [ci][m]

// ============================================================================
//                    fp16 mma + ldmatrix machinery
// ============================================================================
__device__ __forceinline__ u32 packh2(float a, float b) {
    __half2 h = __halves2half2(__float2half_rn(a), __float2half_rn(b));
    return reinterpret_cast<u32&>(h);
}
__device__ __forceinline__ u32 hmul_u32(u32 a, u32 b) {
    __half2 r = __hmul2(reinterpret_cast<__half2&>(a), reinterpret_cast<__half2&>(b));
    return reinterpret_cast<u32&>(r);
}
__device__ __forceinline__ void mma_f16(float c[4], const u32 a[4], const u32 b[2]) {
    asm volatile(
        "mma.sync.aligned.m16n8k16.row.col.f32.f16.f16.f32 "
        "{%0,%1,%2,%3}, {%4,%5,%6,%7}, {%8,%9}, {%0,%1,%2,%3};"
        : "+f"(c[0]), "+f"(c[1]), "+f"(c[2]), "+f"(c[3])
        : "r"(a[0]), "r"(a[1]), "r"(a[2]), "r"(a[3]), "r"(b[0]), "r"(b[1]));
}
#define LDSM4(d, a) \
    asm volatile("ldmatrix.sync.aligned.m8n8.x4.shared.b16 {%0,%1,%2,%3}, [%4];" \
        : "=r"((d)[0]), "=r"((d)[1]), "=r"((d)[2]), "=r"((d)[3]) : "r"(a))
#define LDSM4T(d, a) \
    asm volatile("ldmatrix.sync.aligned.m8n8.x4.trans.shared.b16 {%0,%1,%2,%3}, [%4];" \
        : "=r"((d)[0]), "=r"((d)[1]), "=r"((d)[2]), "=r"((d)[3]) : "r"(a))

__device__ __forceinline__ u32 smem_u32p(const void* p) {
    return (u32)__cvta_generic_to_shared(p);
}
#define CP16(dst, src) asm volatile("cp.async.cg.shared.global [%0], [%1], 16;" :: "r"(dst), "l"(src))
#define CPC()          asm volatile("cp.async.commit_group;")
#define CPW(n)         asm volatile("cp.async.wait_group %0;" :: "n"(n))
#define STS128A(addr, a, b, c, d) \
    asm volatile("st.shared.v4.b32 [%0], {%1,%2,%3,%4};" :: "r"(addr), "r"(a), "r"(b), "r"(c), "r"(d) : "memory")

#define ACC_INIT()                                      \
    float acc[2][8][4];                                 \
    _Pragma("unroll") for (int i = 0; i < 2; i++)       \
    _Pragma("unroll") for (int j = 0; j < 8; j++)       \
    _Pragma("unroll") for (int r = 0; r < 4; r++) acc[i][j][r] = 0.f;

// ldmatrix addr precompute (KTILE = [32 k rows][128 cols] half, 256B rows,
// chunk swizzle c' = c ^ (k&7))
#define KT_ADDRS(adA, adB, base_a, base_b)                               \
    u32 adA[2], adB[4];                                                  \
    {                                                                    \
        const int kA = (lane & 7) + ((lane >> 4) & 1) * 8;               \
        const int oA = (lane >> 3) & 1;                                  \
        _Pragma("unroll")                                                \
        for (int mt = 0; mt < 2; mt++) {                                 \
            const int chk = wm * 4 + mt * 2 + oA;                        \
            adA[mt] = (base_a) + kA * 256 + ((chk ^ (lane & 7)) << 4);   \
        }                                                                \
        const int kB = (lane & 7) + ((lane >> 3) & 1) * 8;               \
        const int oB = (lane >> 4) & 1;                                  \
        _Pragma("unroll")                                                \
        for (int p = 0; p < 4; p++) {                                    \
            const int chk = wn * 8 + p * 2 + oB;                         \
            adB[p] = (base_b) + kB * 256 + ((chk ^ (lane & 7)) << 4);    \
        }                                                                \
    }

#define FCOMP_TT(so)                                                     \
    _Pragma("unroll")                                                    \
    for (int s16 = 0; s16 < 2; ++s16) {                                  \
        const u32 o16 = (so) + s16 * 4096;                               \
        u32 af[2][4], bq[4][4];                                          \
        LDSM4T(af[0], adA[0] + o16);                                     \
        LDSM4T(af[1], adA[1] + o16);                                     \
        _Pragma("unroll")                                                \
        for (int p = 0; p < 4; p++) LDSM4T(bq[p], adB[p] + o16);         \
        _Pragma("unroll")                                                \
        for (int mt = 0; mt < 2; mt++)                                   \
            _Pragma("unroll")                                            \
            for (int p = 0; p < 4; p++) {                                \
                u32 b0[2] = {bq[p][0], bq[p][1]};                        \
                u32 b1[2] = {bq[p][2], bq[p][3]};                        \
                mma_f16(acc[mt][2 * p],     af[mt], b0);                 \
                mma_f16(acc[mt][2 * p + 1], af[mt], b1);                 \
            }                                                            \
    }

#define KT_CP(dstBase, srcPtr, pitch)                                            \
    {                                                                            \
        const int kr = t >> 3, c0k = t & 7;                                      \
        const __half* sp_ = (srcPtr) + (size_t)kr * (pitch);                     \
        CP16((dstBase) + kr * 256 + (((c0k)     ^ (kr & 7)) << 4), sp_ + c0k * 8);       \
        CP16((dstBase) + kr * 256 + (((c0k + 8) ^ (kr & 7)) << 4), sp_ + (c0k + 8) * 8); \
    }

// ---------------- 0: fused packing (x, proj weights, Ww^T) -----------------
#define PX_N (BB * C * NH)          // 1,638,400 u32 stores
#define PW_N (C * 384)              // 98,304 half stores
#define WT_N (CI * C / 2)           // 16,384 u32 stores
__global__ void pack_all_kernel(const float* __restrict__ x,
                                const float* __restrict__ tw,
                                const float* __restrict__ pw,
                                const float* __restrict__ gw,
                                const float* __restrict__ Ww) {
    const int id = blockIdx.x * 256 + threadIdx.x;
    if (id < PX_N) {
        const int n2 = id % NH;
        const int c  = (id / NH) % C;
        const int b  = id / (NH * C);
        const float2 v = *(const float2*)(x + ((size_t)b * C + c) * NN + 2 * n2);
        *(u32*)(d_Xh + ((size_t)b * C + c) * NN + 2 * n2) = packh2(v.x, v.y);
    } else if (id < PX_N + PW_N) {
        const int i = id - PX_N;
        const int c = i / 384, col = i % 384;
        const int which = col >> 7, o = col & 127;
        const float* W = (which == 0) ? tw : (which == 1) ? pw : gw;
        d_Wh[i] = __float2half_rn(W[o * C + c]);
    } else if (id < PX_N + PW_N + WT_N) {
        const int i = id - PX_N - PW_N;
        const int ci = i >> 7, m2 = i & 127;
        *(u32*)(d_Wt + ci * C + 2 * m2) =
            packh2(Ww[(2 * m2) * CI + ci], Ww[(2 * m2 + 1) * CI + ci]);
    }
}

// ---------------- 1: projections (fp16 mma + ldmatrix) ---------------------
// theta/phi: write [c][n] half.  g: write d_GSh [m][c] directly (staged
// transpose through smem, coalesced uint4 stores) -- kills the gscale pass.
__global__ void __launch_bounds__(256, 2) proj_kernel(const float* __restrict__ tb,
                                                      const float* __restrict__ pb,
                                                      const float* __restrict__ gb) {
    __shared__ u32 As[3][2048];
    __shared__ u32 Bs[3][2048];
    const int t = threadIdx.x, lane = t & 31, warp = t >> 5;
    const int wm = warp & 3, wn = warp >> 2;
    const int g = lane >> 2, tig = lane & 3;
    const u32 aB = smem_u32p(As), bB = smem_u32p(Bs);
    KT_ADDRS(adA, adB, aB, bB);

    const int tile = blockIdx.x;                         // 0..299
    const int b = tile / 150;
    const int rem = tile % 150;
    const int which = rem / 50;
    const int n0 = (rem % 50) * 128;
    const __half* Xh = d_Xh + (size_t)b * C * NN;
    const float* bias = (which == 0) ? tb : (which == 1) ? pb : gb;
    ACC_INIT();

    auto issue = [&](int ch, int s) {
        KT_CP(aB + s * 8192, d_Wh + (size_t)(ch * 32) * 384 + which * 128, 384);
        KT_CP(bB + s * 8192, Xh + (size_t)(ch * 32) * NN + n0, NN);
        CPC();
    };
    issue(0, 0); issue(1, 1);
    #pragma unroll
    for (int ch = 0; ch < 8; ++ch) {
        if (ch + 1 < 8) { CPW(1); } else { CPW(0); }
        __syncthreads();
        if (ch + 2 < 8) issue(ch + 2, (ch + 2) % 3);
        FCOMP_TT((ch % 3) * 8192);
    }

    if (which < 2) {
        __half* dst = ((which == 0) ? d_Th : d_Ph) + (size_t)b * CI * NN;
        #pragma unroll
        for (int mt = 0; mt < 2; mt++) {
            const int r = wm * 32 + mt * 16 + g;
            const float bv0 = bias[r], bv8 = bias[r + 8];
            #pragma unroll
            for (int nt = 0; nt < 8; nt++) {
                const int n = n0 + wn * 64 + nt * 8 + tig * 2;
                *(u32*)(dst + (size_t)r * NN + n) =
                    packh2(acc[mt][nt][0] + bv0, acc[mt][nt][1] + bv0);
                *(u32*)(dst + (size_t)(r + 8) * NN + n) =
                    packh2(acc[mt][nt][2] + bv8, acc[mt][nt][3] + bv8);
            }
        }
    } else {
        // g: transpose to [m][c] via smem staging, two 64-row halves.
        u32* st = (u32*)As;                              // 64 x 68 u32 (17.4 KB)
        #pragma unroll
        for (int h = 0; h < 2; h++) {
            __syncthreads();
            if (wn == h) {                               // warp-uniform branch
                #pragma unroll
                for (int mt = 0; mt < 2; mt++) {
                    const int r = wm * 32 + mt * 16 + g; // c index
                    const float bv0 = bias[r], bv8 = bias[r + 8];
                    #pragma unroll
                    for (int nt = 0; nt < 8; nt++) {
                        const int nl = nt * 8 + tig * 2; // m-local within 64
                        const float v0 = acc[mt][nt][0] + bv0;
                        const float v1 = acc[mt][nt][1] + bv0;
                        const float v2 = acc[mt][nt][2] + bv8;
                        const float v3 = acc[mt][nt][3] + bv8;
                        const float p0 = __shfl_xor_sync(0xffffffff, v0, 4);
                        const float p1 = __shfl_xor_sync(0xffffffff, v1, 4);
                        const float p2 = __shfl_xor_sync(0xffffffff, v2, 4);
                        const float p3 = __shfl_xor_sync(0xffffffff, v3, 4);
                        if ((g & 1) == 0) {
                            st[nl * 68 + (r >> 1)]             = packh2(v0, p0);
                            st[(nl + 1) * 68 + (r >> 1)]       = packh2(v1, p1);
                            st[nl * 68 + ((r + 8) >> 1)]       = packh2(v2, p2);
                            st[(nl + 1) * 68 + ((r + 8) >> 1)] = packh2(v3, p3);
                        }
                    }
                }
            }
            __syncthreads();
            #pragma unroll
            for (int rr = 0; rr < 4; rr++) {
                const int idx = t + 256 * rr;            // 0..1023
                const int ml = idx >> 4;                 // 0..63
                const int q4 = (idx & 15) * 4;           // u32 col, 16B aligned
                const uint4 v = *(uint4*)&st[ml * 68 + q4];
                *(uint4*)(d_GSh + ((size_t)b * NN + n0 + h * 64 + ml) * CI + q4 * 2) = v;
            }
        }
    }
}

// ---------------- 2: f = theta^T phi ; store S fp16 + stats ----------------
__global__ void __launch_bounds__(256, 2) fgemm_kernel() {
    __shared__ u32 As[3][2048];
    __shared__ u32 Bs[3][2048];
    const int b  = blockIdx.z;
    const int n0 = blockIdx.y * 128;
    const int m0 = blockIdx.x * 128;
    const __half* Th = d_Th + (size_t)b * CI * NN;
    const __half* Ph = d_Ph + (size_t)b * CI * NN;
    u32* S = d_Sh + (size_t)b * NN * NH;

    const int t = threadIdx.x, lane = t & 31, warp = t >> 5;
    const int wm = warp & 3, wn = warp >> 2;
    const int g = lane >> 2, tig = lane & 3;
    const u32 aB = smem_u32p(As), bB = smem_u32p(Bs);
    KT_ADDRS(adA, adB, aB, bB);
    ACC_INIT();

    auto issue = [&](int ch, int s) {
        KT_CP(aB + s * 8192, Th + (size_t)(ch * 32) * NN + n0, NN);
        KT_CP(bB + s * 8192, Ph + (size_t)(ch * 32) * NN + m0, NN);
        CPC();
    };
    issue(0, 0); issue(1, 1);
    #pragma unroll
    for (int ch = 0; ch < 4; ++ch) {
        if (ch + 1 < 4) { CPW(1); } else { CPW(0); }
        __syncthreads();
        if (ch + 2 < 4) issue(ch + 2, (ch + 2) % 3);
        FCOMP_TT((ch % 3) * 8192);
    }

    // ---- column-softmax (R13 epilogue: combine by 128 threads) ----
    float* red = (float*)As;
    float lv[8][2];
    #pragma unroll
    for (int nt = 0; nt < 8; nt++) {
        lv[nt][0] = fmaxf(fmaxf(acc[0][nt][0], acc[0][nt][2]), fmaxf(acc[1][nt][0], acc[1][nt][2]));
        lv[nt][1] = fmaxf(fmaxf(acc[0][nt][1], acc[0][nt][3]), fmaxf(acc[1][nt][1], acc[1][nt][3]));
        #pragma unroll
        for (int d = 4; d <= 16; d <<= 1) {
            lv[nt][0] = fmaxf(lv[nt][0], __shfl_xor_sync(0xffffffff, lv[nt][0], d));
            lv[nt][1] = fmaxf(lv[nt][1], __shfl_xor_sync(0xffffffff, lv[nt][1], d));
        }
    }
    __syncthreads();
    if (g == 0) {
        #pragma unroll
        for (int nt = 0; nt < 8; nt++) {
            const int col = wn * 64 + nt * 8 + tig * 2;
            red[wm * 128 + col]     = lv[nt][0];
            red[wm * 128 + col + 1] = lv[nt][1];
        }
    }
    __syncthreads();
    if (t < 128) {
        red[512 + t] = fmaxf(fmaxf(red[t], red[128 + t]), fmaxf(red[256 + t], red[384 + t]));
    }
    __syncthreads();
    #pragma unroll
    for (int nt = 0; nt < 8; nt++) {
        const int col = wn * 64 + nt * 8 + tig * 2;
        const float tm0 = red[512 + col], tm1 = red[512 + col + 1];
        float s0 = 0.f, s1 = 0.f;
        #pragma unroll
        for (int mt = 0; mt < 2; mt++) {
            const int n = n0 + wm * 32 + mt * 16 + g;
            const float e0 = __expf(acc[mt][nt][0] - tm0);
            const float e1 = __expf(acc[mt][nt][1] - tm1);
            const float e2 = __expf(acc[mt][nt][2] - tm0);
            const float e3 = __expf(acc[mt][nt][3] - tm1);
            const size_t m2 = (size_t)((m0 + col) >> 1);
            S[(size_t)n * NH + m2]       = packh2(e0, e1);
            S[(size_t)(n + 8) * NH + m2] = packh2(e2, e3);
            s0 += e0 + e2; s1 += e1 + e3;
        }
        #pragma unroll
        for (int d = 4; d <= 16; d <<= 1) {
            s0 += __shfl_xor_sync(0xffffffff, s0, d);
            s1 += __shfl_xor_sync(0xffffffff, s1, d);
        }
        lv[nt][0] = s0; lv[nt][1] = s1;
    }
    __syncthreads();
    if (g == 0) {
        #pragma unroll
        for (int nt = 0; nt < 8; nt++) {
            const int col = wn * 64 + nt * 8 + tig * 2;
            red[wm * 128 + col]     = lv[nt][0];
            red[wm * 128 + col + 1] = lv[nt][1];
        }
    }
    __syncthreads();
    if (t < 128) {
        const float s = red[t] + red[128 + t] + red[256 + t] + red[384 + t];
        const size_t idx = ((size_t)b * NBLK + blockIdx.y) * NN + m0 + t;
        d_pM[idx] = red[512 + t];
        d_pS[idx] = s;
    }
}

// ---------------- 3: merge stats -> corr[nblk][m] half (stats only) --------
__global__ void __launch_bounds__(512) merge_stats_kernel() {
    __shared__ float2 red[16][32];
    __shared__ float2 resM[32], resR[32];
    const int t = threadIdx.x;
    const int id2 = blockIdx.x;
    const int b = id2 / 100;
    const int lane = t & 31, seg = t >> 5;               // seg 0..15
    const int m2 = (id2 % 100) * 32 + lane;
    const float* pM = d_pM + (size_t)b * NBLK * NN + 2 * m2;
    const float* pS = d_pS + (size_t)b * NBLK * NN + 2 * m2;

    float2 vm[4];
    int cnt = 0;
    float M0 = -CUDART_INF_F, M1 = -CUDART_INF_F;
    for (int i = seg; i < NBLK; i += 16) {
        vm[cnt] = *(const float2*)(pM + (size_t)i * NN);
        M0 = fmaxf(M0, vm[cnt].x); M1 = fmaxf(M1, vm[cnt].y);
        cnt++;
    }
    red[seg][lane] = make_float2(M0, M1);
    __syncthreads();
    if (seg == 0) {
        #pragma unroll
        for (int j = 1; j < 16; j++) {
            M0 = fmaxf(M0, red[j][lane].x);
            M1 = fmaxf(M1, red[j][lane].y);
        }
        resM[lane] = make_float2(M0, M1);
    }
    __syncthreads();
    M0 = resM[lane].x; M1 = resM[lane].y;

    float s0 = 0.f, s1 = 0.f;
    {
        int k = 0;
        for (int i = seg; i < NBLK; i += 16, k++) {
            const float2 vs = *(const float2*)(pS + (size_t)i * NN);
            s0 += vs.x * __expf(vm[k].x - M0);
            s1 += vs.y * __expf(vm[k].y - M1);
        }
    }
    red[seg][lane] = make_float2(s0, s1);
    __syncthreads();
    if (seg == 0) {
        #pragma unroll
        for (int j = 1; j < 16; j++) {
            s0 += red[j][lane].x;
            s1 += red[j][lane].y;
        }
        resR[lane] = make_float2(1.f / s0, 1.f / s1);
    }
    __syncthreads();
    const float R0 = resR[lane].x, R1 = resR[lane].y;
    {
        __half* cw = d_corr + (size_t)b * NBLK * NN + 2 * m2;
        int k = 0;
        for (int i = seg; i < NBLK; i += 16, k++)
            *(u32*)(cw + (size_t)i * NN) =
                packh2(__expf(vm[k].x - M0) * R0, __expf(vm[k].y - M1) * R1);
    }
}

// ---------------- 5: y = (S*corr) g  (ldmatrix fp16 mma, split-K) ----------
__global__ void __launch_bounds__(256, 2) ygemm_kernel() {
    __shared__ u32 As[3][2048];                          // S tile [128 n][32 k] half
    __shared__ u32 Bs[3][2048];                          // B' tile [32 k][128 c] half
    const int b     = blockIdx.z;
    const int split = blockIdx.y;
    const int n0    = blockIdx.x * 128;
    const __half* S   = (const __half*)(const void*)(d_Sh + (size_t)b * NN * NH);
    const __half* GSh = d_GSh + (size_t)b * NN * CI;
    const __half* corrh = d_corr + ((size_t)b * NBLK + blockIdx.x) * NN;
    u32* YP = d_YPh + ((size_t)split * BB + b) * NN * (CI / 2);
    const int kbase = split * (NN / SPLITK);             // 800 per split
    const int NCH   = (NN / SPLITK) / 32;                // 25

    const int t = threadIdx.x, lane = t & 31, warp = t >> 5;
    const int wm = warp & 3, wn = warp >> 2;
    const int g = lane >> 2, tig = lane & 3;
    const u32 aB = smem_u32p(As), bB = smem_u32p(Bs);
    ACC_INIT();

    u32 adAy[2][2];
    {
        const int nl = lane & 15, kh = (lane >> 4) & 1;
        #pragma unroll
        for (int mt = 0; mt < 2; mt++) {
            const int n = wm * 32 + mt * 16 + nl;
            #pragma unroll
            for (int s16 = 0; s16 < 2; s16++) {
                const int chk = s16 * 2 + kh;
                adAy[mt][s16] = aB + n * 64 + ((chk ^ ((n >> 1) & 3)) << 4);
            }
        }
    }
    u32 adB[4];
    {
        const int kB = (lane & 7) + ((lane >> 3) & 1) * 8;
        const int oB = (lane >> 4) & 1;
        #pragma unroll
        for (int p = 0; p < 4; p++) {
            const int chk = wn * 8 + p * 2 + oB;
            adB[p] = bB + kB * 256 + ((chk ^ (lane & 7)) << 4);
        }
    }

    auto issueA = [&](int ch, int s) {
        const int nr = t >> 1, cc = (t & 1) * 2;
        const __half* sp = S + (size_t)(n0 + nr) * NN + kbase + ch * 32;
        const u32 dst = aB + s * 8192 + nr * 64;
        CP16(dst + (((cc)     ^ ((nr >> 1) & 3)) << 4), sp + cc * 8);
        CP16(dst + (((cc + 1) ^ ((nr >> 1) & 3)) << 4), sp + (cc + 1) * 8);
        CPC();
    };
    const int rowB = t >> 3, cB = t & 7;
    uint4 gv[2]; __half crh;
    auto ldB = [&](int ch) {
        const int m = kbase + ch * 32 + rowB;
        const __half* gp = GSh + (size_t)m * CI;
        gv[0] = *(const uint4*)(gp + cB * 8);
        gv[1] = *(const uint4*)(gp + (cB + 8) * 8);
        crh = corrh[m];
    };
    auto stsB = [&](int s) {
        const __half2 crs2 = __half2half2(crh);
        const u32 crs = reinterpret_cast<const u32&>(crs2);
        const u32 dst = bB + s * 8192 + rowB * 256;
        #pragma unroll
        for (int i = 0; i < 2; i++) {
            uint4 w = gv[i];
            STS128A(dst + (((cB + 8 * i) ^ (rowB & 7)) << 4),
                    hmul_u32(w.x, crs), hmul_u32(w.y, crs),
                    hmul_u32(w.z, crs), hmul_u32(w.w, crs));
        }
    };

    ldB(0); issueA(0, 0); issueA(1, 1);
    for (int ch = 0; ch < NCH; ++ch) {
        if (ch + 1 < NCH) { CPW(1); } else { CPW(0); }
        stsB(ch % 3);
        __syncthreads();
        if (ch + 1 < NCH) ldB(ch + 1);
        if (ch + 2 < NCH) issueA(ch + 2, (ch + 2) % 3);
        const u32 so = (ch % 3) * 8192;
        #pragma unroll
        for (int s16 = 0; s16 < 2; ++s16) {
            u32 af[2][4], bq[4][4];
            LDSM4(af[0], adAy[0][s16] + so);
            LDSM4(af[1], adAy[1][s16] + so);
            #pragma unroll
            for (int p = 0; p < 4; p++) LDSM4T(bq[p], adB[p] + so + s16 * 4096);
            #pragma unroll
            for (int mt = 0; mt < 2; mt++)
                #pragma unroll
                for (int p = 0; p < 4; p++) {
                    u32 b0[2] = {bq[p][0], bq[p][1]};
                    u32 b1[2] = {bq[p][2], bq[p][3]};
                    mma_f16(acc[mt][2 * p],     af[mt], b0);
                    mma_f16(acc[mt][2 * p + 1], af[mt], b1);
                }
        }
    }

    // packed fp16 partial store: u32 per (n, c-pair)
    #pragma unroll
    for (int mt = 0; mt < 2; mt++) {
        #pragma unroll
        for (int nt = 0; nt < 8; nt++) {
            const int n  = n0 + wm * 32 + mt * 16 + g;
            const int c2 = wn * 32 + nt * 4 + tig;
            YP[(size_t)n * (CI / 2) + c2]       = packh2(acc[mt][nt][0], acc[mt][nt][1]);
            YP[(size_t)(n + 8) * (CI / 2) + c2] = packh2(acc[mt][nt][2], acc[mt][nt][3]);
        }
    }
}

// ---------------- 6: merge fp16 split-K + transpose -> half [c][n] ---------
__global__ void __launch_bounds__(256) reduceY_kernel() {
    __shared__ float tsm[64][33];                        // [c-local][n-local]
    const int b  = blockIdx.z;
    const int n0 = blockIdx.x * 32;
    const int c0 = blockIdx.y * 64;
    const int t  = threadIdx.x;
    const size_t SS = (size_t)BB * NN * (CI / 2);
    const size_t base = (size_t)b * NN * (CI / 2);
    #pragma unroll
    for (int r = 0; r < 4; r++) {
        const int idx = t + 256 * r;                     // 0..1023
        const int nl = idx >> 5;                         // 0..31
        const int cp = idx & 31;                         // c2-local 0..31
        const size_t off = base + (size_t)(n0 + nl) * (CI / 2) + (c0 >> 1) + cp;
        float s0 = 0.f, s1 = 0.f;
        #pragma unroll
        for (int sp = 0; sp < SPLITK; sp++) {
            const u32 w = d_YPh[sp * SS + off];
            const __half2 h = reinterpret_cast<const __half2&>(w);
            s0 += __low2float(h); s1 += __high2float(h);
        }
        tsm[2 * cp][nl] = s0; tsm[2 * cp + 1][nl] = s1;
    }
    __syncthreads();
    #pragma unroll
    for (int r = 0; r < 4; r++) {
        const int idx = t + 256 * r;
        const int cl = idx >> 4;                         // 0..63
        const int np = idx & 15;                         // 0..15
        *(u32*)(d_Yh + ((size_t)b * CI + c0 + cl) * NN + n0 + 2 * np) =
            packh2(tsm[cl][2 * np], tsm[cl][2 * np + 1]);
    }
}

// ---------------- 9: out = Ww·y + Wb + x  (ldmatrix fp16 mma) --------------
__global__ void __launch_bounds__(256, 2) out_kernel(const float* __restrict__ x,
                                                     const float* __restrict__ Wb,
                                                     float* __restrict__ out) {
    __shared__ u32 As[3][2048];
    __shared__ u32 Bs[3][2048];
    const int b  = blockIdx.z;
    const int m0 = blockIdx.y * 128;
    const int n0 = blockIdx.x * 128;
    const __half* Yh = d_Yh + (size_t)b * CI * NN;

    const int t = threadIdx.x, lane = t & 31, warp = t >> 5;
    const int wm = warp & 3, wn = warp >> 2;
    const int g = lane >> 2, tig = lane & 3;
    const u32 aB = smem_u32p(As), bB = smem_u32p(Bs);
    KT_ADDRS(adA, adB, aB, bB);
    ACC_INIT();

    auto issue = [&](int ch, int s) {
        KT_CP(aB + s * 8192, d_Wt + (size_t)(ch * 32) * C + m0, C);
        KT_CP(bB + s * 8192, Yh + (size_t)(ch * 32) * NN + n0, NN);
        CPC();
    };
    issue(0, 0); issue(1, 1);
    #pragma unroll
    for (int ch = 0; ch < 4; ++ch) {
        if (ch + 1 < 4) { CPW(1); } else { CPW(0); }
        __syncthreads();
        if (ch + 2 < 4) issue(ch + 2, (ch + 2) % 3);
        FCOMP_TT((ch % 3) * 8192);
    }

    #pragma unroll
    for (int mt = 0; mt < 2; mt++) {
        #pragma unroll
        for (int nt = 0; nt < 8; nt++) {
            const int m = m0 + wm * 32 + mt * 16 + g;
            const int n = n0 + wn * 64 + nt * 8 + tig * 2;
            {
                const float bv = Wb[m];
                const float2 xv = *(const float2*)(x + ((size_t)b * C + m) * NN + n);
                *(float2*)(out + ((size_t)b * C + m) * NN + n) =
                    make_float2(acc[mt][nt][0] + bv + xv.x, acc[mt][nt][1] + bv + xv.y);
            }
            {
                const float bv = Wb[m + 8];
                const float2 xv = *(const float2*)(x + ((size_t)b * C + m + 8) * NN + n);
                *(float2*)(out + ((size_t)b * C + m + 8) * NN + n) =
                    make_float2(acc[mt][nt][2] + bv + xv.x, acc[mt][nt][3] + bv + xv.y);
            }
        }
    }
}

// ---------------------------------------------------------------------------
extern "C" void kernel_launch(void* const* d_in, const int* in_sizes, int n_in,
                              void* d_out, int out_size) {
    const float* x  = (const float*)d_in[0];
    const float* gw = (const float*)d_in[1];
    const float* gb = (const float*)d_in[2];
    const float* tw = (const float*)d_in[3];
    const float* tb = (const float*)d_in[4];
    const float* pw = (const float*)d_in[5];
    const float* pb = (const float*)d_in[6];
    const float* Ww = (const float*)d_in[7];
    const float* Wb = (const float*)d_in[8];
    float* out = (float*)d_out;

    pack_all_kernel<<<(PX_N + PW_N + WT_N + 255) / 256, 256>>>(x, tw, pw, gw, Ww);
    proj_kernel<<<300, 256>>>(tb, pb, gb);
    fgemm_kernel<<<dim3(NN / 128, NN / 128, BB), 256>>>();
    merge_stats_kernel<<<100 * BB, 512>>>();
    ygemm_kernel<<<dim3(NN / 128, SPLITK, BB), 256>>>();
    reduceY_kernel<<<dim3(NN / 32, CI / 64, BB), 256>>>();
    out_kernel<<<dim3(NN / 128, C / 128, BB), 256>>>(x, Wb, out);
}